// round 6
// baseline (speedup 1.0000x reference)
#include <cuda_runtime.h>
#include <stdint.h>

// FieldAwareFM: B=16384, F=10, D=8.
// out[b] = b_lin + sum_f w[idx_f] + sum_{f<g} <emb[f][idx_g], emb[g][idx_f]>
//
// Bound by scattered 32B-sector count (~90/sample), invariant to gather
// mechanism (R1-R4). This round: fields 8 (dim 100) and 9 (dim 10) are the
// gather column in 18 of 90 loads/sample; their full footprint across ALL 10
// tables (10x100x32B + 10x10x32B = 35.2KB) is staged in smem per block, so
// those gathers become LDS. (R5 bug: only tables 0..8 were staged; pair (8,9)
// role 1 needs table 9 -> now stage all 10.)
//
// Lane layout per round t: slot p = 8t + (lane>>2); role=(lane>>1)&1 picks
// emb[f][idx_g] vs emb[g][idx_f]; half=lane&1 picks 16B of the 32B row.
// shfl_xor(2) swaps roles; every pair dot computed twice -> *0.5.

#define BATCH      16384
#define NUM_FIELDS 10
#define INPUT_DIM  188610
#define NUM_PAIRS  45
#define NUM_ROUNDS 6

// smem cache (floats): field-8 rows [0,8000): table f at f*800, row r at +r*8
//                      field-9 rows [8000,8800): table f at f*80, row r at +r*8
//                      w tail [8800,8912): w8 at +0 (100), w9 at +100 (10)
#define SC8_BASE   0
#define SC9_BASE   8000
#define SW_BASE    8800
#define SC_FLOATS  8912
#define OFF8       188500
#define OFF9       188600

__constant__ int c_offsets[NUM_FIELDS] = {
    0, 100000, 150000, 170000, 180000, 185000, 187000, 188000, 188500, 188600
};

// c_tbl[2p + role]: low nibble = embedding-table index (row), high nibble =
// index-field (col). role 0: (g<<4)|f   role 1: (f<<4)|g
// pads p=45..47 -> 0x00 (harmless gmem load, masked in accumulate)
__constant__ unsigned char c_tbl[2 * 48] = {
    0x10,0x01, 0x20,0x02, 0x30,0x03, 0x40,0x04, 0x50,0x05, 0x60,0x06, 0x70,0x07, 0x80,0x08,
    0x90,0x09, 0x21,0x12, 0x31,0x13, 0x41,0x14, 0x51,0x15, 0x61,0x16, 0x71,0x17, 0x81,0x18,
    0x91,0x19, 0x32,0x23, 0x42,0x24, 0x52,0x25, 0x62,0x26, 0x72,0x27, 0x82,0x28, 0x92,0x29,
    0x43,0x34, 0x53,0x35, 0x63,0x36, 0x73,0x37, 0x83,0x38, 0x93,0x39, 0x54,0x45, 0x64,0x46,
    0x74,0x47, 0x84,0x48, 0x94,0x49, 0x65,0x56, 0x75,0x57, 0x85,0x58, 0x95,0x59, 0x76,0x67,
    0x86,0x68, 0x96,0x69, 0x87,0x78, 0x97,0x79, 0x98,0x89, 0x00,0x00, 0x00,0x00, 0x00,0x00
};

__global__ __launch_bounds__(256)
void ffm_kernel(const int* __restrict__ x,
                const float* __restrict__ w,
                const float* __restrict__ b_lin,
                const float* __restrict__ emb,
                float* __restrict__ out)
{
    __shared__ __align__(16) float scache[SC_FLOATS];

    const int tid  = threadIdx.x;
    const int lane = tid & 31;
    const int warp = tid >> 5;
    const unsigned full = 0xffffffffu;

    // ---- stage ALL 10 tables' field-8/9 rows + w tail into smem ----
    {
        // field 8: 10 tables x 100 rows x 2 float4 = 2000 float4
        for (int j = tid; j < 2000; j += 256) {
            const int f = j / 200, within = j % 200;
            const float* src = emb + ((size_t)f * INPUT_DIM + OFF8) * 8 + within * 4;
            ((float4*)(scache + SC8_BASE))[j] = *(const float4*)src;
        }
        // field 9: 10 tables x 10 rows x 2 float4 = 200 float4
        for (int j = tid; j < 200; j += 256) {
            const int f = j / 20, within = j % 20;
            const float* src = emb + ((size_t)f * INPUT_DIM + OFF9) * 8 + within * 4;
            ((float4*)(scache + SC9_BASE))[j] = *(const float4*)src;
        }
        if (tid < 110) {
            scache[SW_BASE + tid] = (tid < 100) ? __ldg(&w[OFF8 + tid])
                                                : __ldg(&w[OFF9 + tid - 100]);
        }
    }
    __syncthreads();

    const float bias = __ldg(&b_lin[0]);
    const char* embc = (const char*)emb;

    // ---- per-lane slot decode (constant across samples) ----
    const int q    = lane >> 2;
    const int half = lane & 1;
    uint32_t off[NUM_ROUNDS];   // smem float-offset (row base) or gmem byte-offset
    int      col[NUM_ROUNDS];
    bool     smr[NUM_ROUNDS];
#pragma unroll
    for (int t = 0; t < NUM_ROUNDS; t++) {
        const int e   = (int)c_tbl[(((t * 8 + q) << 1) | ((lane >> 1) & 1))];
        const int row = e & 15;
        const int c   = e >> 4;
        col[t] = c;
        smr[t] = (c >= 8);
        if (c == 8)      off[t] = (uint32_t)(SC8_BASE + row * 800);
        else if (c == 9) off[t] = (uint32_t)(SC9_BASE + row * 80);
        else             off[t] = (uint32_t)((row * INPUT_DIM + c_offsets[c]) * 32);
    }

    // ---- two samples per warp ----
    const int b0 = blockIdx.x * 16 + warp;   // grid=1024, 16 samples/block
    const int b1 = b0 + 8;
    const int bs[2] = { b0, b1 };

    int   raw[2];
    float lin[2];
#pragma unroll
    for (int s = 0; s < 2; s++) {
        int r = 0;
        if (lane < NUM_FIELDS) r = x[bs[s] * NUM_FIELDS + lane];
        raw[s] = r;
        float l = 0.0f;
        if (lane < 8)               l = __ldg(&w[r + c_offsets[lane]]);
        else if (lane < NUM_FIELDS) l = scache[SW_BASE + ((lane == 8) ? 0 : 100) + r];
        lin[s] = l;
    }

    // ---- Phase A: issue all 12 gathers (both samples, batched) ----
    float4 v[2][NUM_ROUNDS];
#pragma unroll
    for (int s = 0; s < 2; s++) {
#pragma unroll
        for (int t = 0; t < NUM_ROUNDS; t++) {
            const int idx = __shfl_sync(full, raw[s], col[t]);
            if (smr[t]) {
                v[s][t] = *(const float4*)&scache[off[t] + idx * 8 + half * 4];
            } else {
                v[s][t] = __ldg((const float4*)(embc + off[t] + (size_t)idx * 32 + half * 16));
            }
        }
    }

    // ---- Phase B: role exchange + dot accumulate, reduce, store ----
#pragma unroll
    for (int s = 0; s < 2; s++) {
        float ffm = 0.0f;
#pragma unroll
        for (int t = 0; t < NUM_ROUNDS; t++) {
            float ux = __shfl_xor_sync(full, v[s][t].x, 2);
            float uy = __shfl_xor_sync(full, v[s][t].y, 2);
            float uz = __shfl_xor_sync(full, v[s][t].z, 2);
            float uw = __shfl_xor_sync(full, v[s][t].w, 2);
            float d  = v[s][t].x * ux + v[s][t].y * uy + v[s][t].z * uz + v[s][t].w * uw;
            if ((t * 8 + q) < NUM_PAIRS) ffm += d;
        }
        float acc = 0.5f * ffm + lin[s];
#pragma unroll
        for (int o = 16; o > 0; o >>= 1) {
            acc += __shfl_xor_sync(full, acc, o);
        }
        if (lane == 0) out[bs[s]] = acc + bias;
    }
}

extern "C" void kernel_launch(void* const* d_in, const int* in_sizes, int n_in,
                              void* d_out, int out_size)
{
    (void)in_sizes; (void)n_in; (void)out_size;
    const int*   x     = (const int*)d_in[0];
    const float* w     = (const float*)d_in[1];
    const float* b_lin = (const float*)d_in[2];
    const float* emb   = (const float*)d_in[3];
    float*       out   = (float*)d_out;

    ffm_kernel<<<1024, 256>>>(x, w, b_lin, emb, out);   // 16 samples per block
}

// round 7
// speedup vs baseline: 1.3249x; 1.3249x over previous
#include <cuda_runtime.h>
#include <stdint.h>

// FieldAwareFM: B=16384, F=10, D=8.
// out[b] = b_lin + sum_f w[idx_f] + sum_{f<g} <emb[f][idx_g], emb[g][idx_f]>
//
// R1-R6 showed runtime is invariant (~19us) to gather mechanism and cache
// state -> limiter is the per-SM MIO/L1tex wavefront pipe (LDG wavefronts,
// LDS, and SHFL all share it). This round minimizes MIO ops per sample:
//
// Half-split pair layout (NO role-exchange shuffles):
//   slot = 32t + lane, t in 0..2; pair p = slot>>1 (0..44 valid), h = slot&1.
//   Lane loads emb[f][idx_g][4h..4h+3] and emb[g][idx_f][4h..4h+3] and
//   accumulates the 4-term partial of <row_fg, row_gf> locally; the h=0/h=1
//   partials combine in the final warp reduction (already paid).
//   Adjacent lanes (h=0,1 of same pair) hit the same 128B line -> each row
//   still costs exactly 1 L1 wavefront; gather wavefronts stay at the
//   intrinsic ~90/sample. Shuffles drop 39 -> 11 per sample.

#define BATCH      16384
#define NUM_FIELDS 10
#define INPUT_DIM  188610
#define NUM_PAIRS  45
#define NUM_ROUNDS 3

__constant__ int c_offsets[NUM_FIELDS] = {
    0, 100000, 150000, 170000, 180000, 185000, 187000, 188000, 188500, 188600
};

// pair p -> (f, g), f < g   (pad p=45..47 -> (0,1), masked in accumulate)
__constant__ signed char c_pf[48] = {
    0,0,0,0,0,0,0,0,0,
    1,1,1,1,1,1,1,1,
    2,2,2,2,2,2,2,
    3,3,3,3,3,3,
    4,4,4,4,4,
    5,5,5,5,
    6,6,6,
    7,7,
    8,
    0,0,0
};
__constant__ signed char c_pg[48] = {
    1,2,3,4,5,6,7,8,9,
    2,3,4,5,6,7,8,9,
    3,4,5,6,7,8,9,
    4,5,6,7,8,9,
    5,6,7,8,9,
    6,7,8,9,
    7,8,9,
    8,9,
    9,
    1,1,1
};

__global__ __launch_bounds__(256)
void ffm_kernel(const int* __restrict__ x,
                const float* __restrict__ w,
                const float* __restrict__ b_lin,
                const float* __restrict__ emb,
                float* __restrict__ out)
{
    const int warp_in_block = threadIdx.x >> 5;
    const int lane          = threadIdx.x & 31;
    const int b             = blockIdx.x * (blockDim.x >> 5) + warp_in_block;
    const unsigned full     = 0xffffffffu;

    const float bias = __ldg(&b_lin[0]);

    // lanes 0..9: this sample's global indices (coalesced 40B)
    int my_idx = 0;
    if (lane < NUM_FIELDS) {
        my_idx = x[b * NUM_FIELDS + lane] + c_offsets[lane];
    }
    // linear term gather (independent, issues early)
    float lin = 0.0f;
    if (lane < NUM_FIELDS) {
        lin = __ldg(&w[my_idx]);
    }

    const int h = lane & 1;               // half of the 32B row (16B)

    // ---- Phase A: decode slots, 2 shuffles/round, issue all 6 loads ----
    const float4* pa[NUM_ROUNDS];
    const float4* pb[NUM_ROUNDS];
    bool valid[NUM_ROUNDS];
#pragma unroll
    for (int t = 0; t < NUM_ROUNDS; t++) {
        const int p = ((t << 5) + lane) >> 1;          // pair index
        const int f = (int)c_pf[p];
        const int g = (int)c_pg[p];
        const int idx_g = __shfl_sync(full, my_idx, g);
        const int idx_f = __shfl_sync(full, my_idx, f);
        valid[t] = (p < NUM_PAIRS);
        pa[t] = (const float4*)(emb + ((size_t)f * INPUT_DIM + (size_t)idx_g) * 8) + h;
        pb[t] = (const float4*)(emb + ((size_t)g * INPUT_DIM + (size_t)idx_f) * 8) + h;
    }

    float4 va[NUM_ROUNDS], vb[NUM_ROUNDS];
#pragma unroll
    for (int t = 0; t < NUM_ROUNDS; t++) {
        va[t] = __ldg(pa[t]);
        vb[t] = __ldg(pb[t]);
    }

    // ---- Phase B: local partial dots (no exchange) ----
    float ffm = 0.0f;
#pragma unroll
    for (int t = 0; t < NUM_ROUNDS; t++) {
        float d = va[t].x * vb[t].x + va[t].y * vb[t].y
                + va[t].z * vb[t].z + va[t].w * vb[t].w;
        if (valid[t]) ffm += d;
    }

    float acc = ffm + lin;

    // warp reduction (combines pair halves + linear lanes)
#pragma unroll
    for (int off = 16; off > 0; off >>= 1) {
        acc += __shfl_xor_sync(full, acc, off);
    }

    if (lane == 0) {
        out[b] = acc + bias;
    }
}

extern "C" void kernel_launch(void* const* d_in, const int* in_sizes, int n_in,
                              void* d_out, int out_size)
{
    (void)in_sizes; (void)n_in; (void)out_size;
    const int*   x     = (const int*)d_in[0];
    const float* w     = (const float*)d_in[1];
    const float* b_lin = (const float*)d_in[2];
    const float* emb   = (const float*)d_in[3];
    float*       out   = (float*)d_out;

    const int warps_per_block = 8;              // 256 threads
    const int blocks = BATCH / warps_per_block; // 2048
    ffm_kernel<<<blocks, warps_per_block * 32>>>(x, w, b_lin, emb, out);
}